// round 9
// baseline (speedup 1.0000x reference)
#include <cuda_runtime.h>
#include <math.h>
#include <cstdint>

#define SEQL   2048
#define NHEAD  8
#define DMODEL 512
#define HDIM   64
#define CATD   128
#define NHTOT  16

// Scratch (allocation-free). Values stored pre-rounded to tf32 bit patterns.
__device__ float g_A [(size_t)NHTOT * SEQL * CATD];   // [nh][l][c]   A operand (K-major)
__device__ float g_B [(size_t)NHTOT * SEQL * CATD];   // [nh][l][c]   B operand (K-major)
__device__ float g_Vt[(size_t)NHTOT * HDIM * SEQL];   // [nh][d][l]   stage-2 B operand (K-major)

#define DINL __device__ __forceinline__

DINL uint32_t f2tf(float f) {           // round fp32 -> tf32 (rna), fp32 bit layout
    uint32_t u;
    asm("cvt.rna.tf32.f32 %0, %1;" : "=r"(u) : "f"(f));
    return u;
}

// m16n8k8 tf32 MMA, fp32 accumulate (legacy mma.sync path, base sm_103 ISA)
DINL void mma8(float* d, const uint32_t* a, const uint32_t* b) {
    asm volatile("mma.sync.aligned.m16n8k8.row.col.f32.tf32.tf32.f32 "
        "{%0,%1,%2,%3}, {%4,%5,%6,%7}, {%8,%9}, {%0,%1,%2,%3};"
        : "+f"(d[0]), "+f"(d[1]), "+f"(d[2]), "+f"(d[3])
        : "r"(a[0]), "r"(a[1]), "r"(a[2]), "r"(a[3]), "r"(b[0]), "r"(b[1]));
}

DINL uint32_t smem_u32(const void* p) {
    uint32_t a;
    asm("{ .reg .u64 t; cvta.to.shared.u64 t, %1; cvt.u32.u64 %0, t; }" : "=r"(a) : "l"(p));
    return a;
}
DINL void cp16(uint32_t dst, const void* src) {
    asm volatile("cp.async.cg.shared.global [%0], [%1], 16;" :: "r"(dst), "l"(src));
}
#define CP_COMMIT() asm volatile("cp.async.commit_group;" ::: "memory")
#define CP_WAIT(N)  asm volatile("cp.async.wait_group %0;" :: "n"(N) : "memory")

DINL float softplus_f(float x) {
    return fmaxf(x, 0.f) + log1pf(__expf(-fabsf(x)));
}
DINL void sincos_red(float ang, float* s, float* c) {
    const float INV2PI = 0.15915494309189535f;
    const float PI2_HI = 6.28318548202514648f;
    const float PI2_LO = -1.74845553e-7f;
    float k = rintf(ang * INV2PI);
    float r = fmaf(-k, PI2_HI, ang);
    r = fmaf(-k, PI2_LO, r);
    *s = __sinf(r);
    *c = __cosf(r);
}

// ─────────────────────────── Projection GEMM (tf32 mma.sync) ────────────────
// Unchanged (known-good). C(128x128) = X·W^T over K=512, slabs of 64.
#define PJ_PITCH 68
#define PJ_SMEM  (2 * 128 * PJ_PITCH * 4)

__global__ __launch_bounds__(256, 2) void proj_tc(
    const float* __restrict__ query, const float* __restrict__ key,
    const float* __restrict__ Wq, const float* __restrict__ Wk, const float* __restrict__ Wv,
    const float* __restrict__ coeff, const float* __restrict__ pw, const float* __restrict__ pb)
{
    extern __shared__ float sm[];
    float (*Xs)[PJ_PITCH] = (float(*)[PJ_PITCH])sm;
    float (*Ws)[PJ_PITCH] = (float(*)[PJ_PITCH])(sm + 128 * PJ_PITCH);

    int tid = threadIdx.x, wid = tid >> 5, lane = tid & 31;
    int warpM = wid >> 1, warpN = wid & 1;
    int g = lane >> 2, t = lane & 3;
    int mode = blockIdx.z;
    const float* X = (mode == 0) ? query : key;
    const float* W = (mode == 0) ? Wq : (mode == 1 ? Wk : Wv);
    int m0 = blockIdx.x * 128;
    int c0 = blockIdx.y * 128;

    float acc[2][8][4];
    #pragma unroll
    for (int mb = 0; mb < 2; ++mb)
        #pragma unroll
        for (int nb = 0; nb < 8; ++nb)
            #pragma unroll
            for (int r = 0; r < 4; ++r) acc[mb][nb][r] = 0.f;

    for (int kc = 0; kc < 8; ++kc) {
        __syncthreads();
        #pragma unroll
        for (int it = 0; it < 8; ++it) {
            int idx = it * 256 + tid;
            int r = idx >> 4, c4 = (idx & 15) * 4;
            float4 vx = *(const float4*)(X + (size_t)(m0 + r) * DMODEL + kc * 64 + c4);
            Xs[r][c4 + 0] = __uint_as_float(f2tf(vx.x));
            Xs[r][c4 + 1] = __uint_as_float(f2tf(vx.y));
            Xs[r][c4 + 2] = __uint_as_float(f2tf(vx.z));
            Xs[r][c4 + 3] = __uint_as_float(f2tf(vx.w));
            float4 vw = *(const float4*)(W + (size_t)(c0 + r) * DMODEL + kc * 64 + c4);
            Ws[r][c4 + 0] = __uint_as_float(f2tf(vw.x));
            Ws[r][c4 + 1] = __uint_as_float(f2tf(vw.y));
            Ws[r][c4 + 2] = __uint_as_float(f2tf(vw.z));
            Ws[r][c4 + 3] = __uint_as_float(f2tf(vw.w));
        }
        __syncthreads();

        #pragma unroll
        for (int ks = 0; ks < 8; ++ks) {
            int k = ks * 8;
            uint32_t a[2][4];
            #pragma unroll
            for (int mb = 0; mb < 2; ++mb) {
                int r0 = warpM * 32 + mb * 16;
                a[mb][0] = __float_as_uint(Xs[r0 + g][k + t]);
                a[mb][1] = __float_as_uint(Xs[r0 + g + 8][k + t]);
                a[mb][2] = __float_as_uint(Xs[r0 + g][k + t + 4]);
                a[mb][3] = __float_as_uint(Xs[r0 + g + 8][k + t + 4]);
            }
            uint32_t b[8][2];
            #pragma unroll
            for (int nb = 0; nb < 8; ++nb) {
                int n0 = warpN * 64 + nb * 8;
                b[nb][0] = __float_as_uint(Ws[n0 + g][k + t]);
                b[nb][1] = __float_as_uint(Ws[n0 + g][k + t + 4]);
            }
            #pragma unroll
            for (int mb = 0; mb < 2; ++mb)
                #pragma unroll
                for (int nb = 0; nb < 8; ++nb)
                    mma8(acc[mb][nb], a[mb], b[nb]);
        }
    }

    // epilogue
    #pragma unroll
    for (int mb = 0; mb < 2; ++mb) {
        #pragma unroll
        for (int nb = 0; nb < 8; ++nb) {
            #pragma unroll
            for (int r = 0; r < 4; ++r) {
                int row = warpM * 32 + mb * 16 + g + (r >> 1) * 8;
                int col = warpN * 64 + nb * 8 + 2 * t + (r & 1);
                int m = m0 + row;
                int n = m >> 11, l = m & (SEQL - 1);
                int c = c0 + col;
                int h = c >> 6, dd = c & 63;
                float x = acc[mb][nb][r];
                if (mode == 2) {
                    g_Vt[((size_t)((n * NHEAD + h) * HDIM + dd)) * SEQL + l] =
                        __uint_as_float(f2tf(x));
                } else {
                    size_t base = ((size_t)(n * NHEAD + h) * SEQL + l) * CATD;
                    float w = pw[c];
                    float sn, cs;
                    if (mode == 0) {
                        float sp = softplus_f(x);
                        sincos_red((float)l * w + pb[c], &sn, &cs);
                        g_A[base + dd]      = __uint_as_float(f2tf(sp * cs));
                        g_A[base + 64 + dd] = __uint_as_float(f2tf(sp * sn));
                    } else {
                        float sp = softplus_f(x) * coeff[c];
                        sincos_red((float)l * w, &sn, &cs);
                        g_B[base + dd]      = __uint_as_float(f2tf(sp * cs));
                        g_B[base + 64 + dd] = __uint_as_float(f2tf(sp * sn));
                    }
                }
            }
        }
    }
}

// ─────────────────────────── Attention (tf32 mma.sync, pipelined) ───────────
// 128 threads, 4 warps, warp tile 16(q) x 64(k). Double-buffered B + prefetch:
//   top of kt: issue {V(kt), B(kt+1)->nxt} as one cp.async group;
//              wait_group 1 retires B(kt) (prefetched a full chunk earlier);
//   mma1 on B[cur]; epilogue (mask/|S|/store S warp-private);
//   wait_group 0 (V arrived during mma1); mma2; barrier.
// smem 100KB -> 2 CTAs/SM.
#define AP 132
#define VP 68
#define SP 68
#define F_B0  0
#define F_B1  (64 * AP)                       // 8448
#define F_V   (2 * 64 * AP)                   // 16896
#define F_S   (2 * 64 * AP + 64 * VP)         // 21248
#define AT_SMEM ((2 * 64 * AP + 64 * VP + 4 * 16 * SP) * 4)   // 102400 bytes

__global__ __launch_bounds__(128, 2) void attn_tc(float* __restrict__ out)
{
    extern __shared__ float sm[];
    float (*Vs)[VP] = (float(*)[VP])(sm + F_V);

    int tid = threadIdx.x, wid = tid >> 5, lane = tid & 31;
    int g = lane >> 2, t = lane & 3;
    int wr = wid * 16;                                  // warp's q-row base (local)
    float (*Ssw)[SP] = (float(*)[SP])(sm + F_S + wid * 16 * SP);  // warp-private

    int nh = blockIdx.y;
    int n = nh >> 3, h = nh & 7;
    int qt = (int)gridDim.x - 1 - (int)blockIdx.x;      // heavy tiles first
    int q0 = qt * 64;

    const float* Ab = g_A  + (size_t)nh * SEQL * CATD;
    const float* Bb = g_B  + (size_t)nh * SEQL * CATD;
    const float* Vb = g_Vt + (size_t)nh * HDIM * SEQL;

    uint32_t smu = smem_u32(sm);
    uint32_t bbuf_u[2] = { smu + F_B0 * 4, smu + F_B1 * 4 };
    float (*bbuf[2])[AP] = { (float(*)[AP])(sm + F_B0), (float(*)[AP])(sm + F_B1) };

    // ── stage A tile (64x128) into B0, pull a-frags to regs ──
    #pragma unroll
    for (int it = 0; it < 16; ++it) {
        int idx = it * 128 + tid;
        int r = idx >> 5, c4 = (idx & 31) * 4;
        cp16(bbuf_u[0] + (uint32_t)(r * AP + c4) * 4, Ab + (size_t)(q0 + r) * CATD + c4);
    }
    CP_COMMIT(); CP_WAIT(0);
    __syncthreads();

    uint32_t a[16][4];
    #pragma unroll
    for (int ks = 0; ks < 16; ++ks) {
        int k = ks * 8;
        a[ks][0] = __float_as_uint(bbuf[0][wr + g][k + t]);
        a[ks][1] = __float_as_uint(bbuf[0][wr + g + 8][k + t]);
        a[ks][2] = __float_as_uint(bbuf[0][wr + g][k + t + 4]);
        a[ks][3] = __float_as_uint(bbuf[0][wr + g + 8][k + t + 4]);
    }
    __syncthreads();          // all warps done reading B0 before B(0) overwrites it

    // ── prologue: B(0) -> B0 (own group) ──
    #pragma unroll
    for (int it = 0; it < 16; ++it) {
        int idx = it * 128 + tid;
        int r = idx >> 5, c4 = (idx & 31) * 4;
        cp16(bbuf_u[0] + (uint32_t)(r * AP + c4) * 4, Bb + (size_t)r * CATD + c4);
    }
    CP_COMMIT();

    float O[8][4];
    #pragma unroll
    for (int nb = 0; nb < 8; ++nb)
        #pragma unroll
        for (int r = 0; r < 4; ++r) O[nb][r] = 0.f;
    float asum[2] = {0.f, 0.f};

    for (int kt = 0; kt <= qt; ++kt) {
        int k0 = kt * 64;
        int cur = kt & 1, nxt = cur ^ 1;

        // ── issue V(kt) + B(kt+1) as ONE group ──
        // V region free: end-of-prev-iter barrier. B[nxt] free: prev post-mma2 barrier.
        #pragma unroll
        for (int it = 0; it < 8; ++it) {
            int idx = it * 128 + tid;
            int r = idx >> 4, c4 = (idx & 15) * 4;
            cp16(smu + (uint32_t)(F_V + r * VP + c4) * 4, Vb + (size_t)r * SEQL + k0 + c4);
        }
        if (kt < qt) {
            #pragma unroll
            for (int it = 0; it < 16; ++it) {
                int idx = it * 128 + tid;
                int r = idx >> 5, c4 = (idx & 31) * 4;
                cp16(bbuf_u[nxt] + (uint32_t)(r * AP + c4) * 4,
                     Bb + (size_t)(k0 + 64 + r) * CATD + c4);
            }
        }
        CP_COMMIT();
        CP_WAIT(1);           // retire B(kt)'s group (in flight since prev chunk)
        __syncthreads();

        // ── mma1: S(16x64) = A · B^T over catd=128 (a-frags in regs) ──
        float (*Bc)[AP] = bbuf[cur];
        float S[8][4];
        #pragma unroll
        for (int nb = 0; nb < 8; ++nb)
            #pragma unroll
            for (int r = 0; r < 4; ++r) S[nb][r] = 0.f;

        #pragma unroll 4
        for (int ks = 0; ks < 16; ++ks) {
            int k = ks * 8;
            uint32_t b[8][2];
            #pragma unroll
            for (int nb = 0; nb < 8; ++nb) {
                int n0 = nb * 8;
                b[nb][0] = __float_as_uint(Bc[n0 + g][k + t]);
                b[nb][1] = __float_as_uint(Bc[n0 + g][k + t + 4]);
            }
            #pragma unroll
            for (int nb = 0; nb < 8; ++nb)
                mma8(S[nb], a[ks], b[nb]);
        }

        // ── epilogue: mask + |S| accumulation + S (tf32) into warp-private Ssw ──
        bool diag = (kt == qt);
        #pragma unroll
        for (int nb = 0; nb < 8; ++nb) {
            int col = nb * 8 + 2 * t;
            #pragma unroll
            for (int rh = 0; rh < 2; ++rh) {
                int rowl = g + rh * 8;
                float v0 = S[nb][rh * 2 + 0];
                float v1 = S[nb][rh * 2 + 1];
                if (diag) {
                    int qg = wr + rowl;
                    if (col + 0 > qg) v0 = 0.f;
                    if (col + 1 > qg) v1 = 0.f;
                }
                asum[rh] += fabsf(v0) + fabsf(v1);
                float2 st;
                st.x = __uint_as_float(f2tf(v0));
                st.y = __uint_as_float(f2tf(v1));
                *(float2*)&Ssw[rowl][col] = st;
            }
        }
        __syncwarp();

        CP_WAIT(0);           // V(kt) + B(kt+1) arrived (issued ~1.5K cyc ago)
        __syncthreads();

        // ── mma2: O(16x64) += S · Vt^T over 64 keys ──
        #pragma unroll 4
        for (int ks = 0; ks < 8; ++ks) {
            int k = ks * 8;
            uint32_t a2[4];
            a2[0] = __float_as_uint(Ssw[g][k + t]);
            a2[1] = __float_as_uint(Ssw[g + 8][k + t]);
            a2[2] = __float_as_uint(Ssw[g][k + t + 4]);
            a2[3] = __float_as_uint(Ssw[g + 8][k + t + 4]);
            uint32_t b[8][2];
            #pragma unroll
            for (int nb = 0; nb < 8; ++nb) {
                int n0 = nb * 8;
                b[nb][0] = __float_as_uint(Vs[n0 + g][k + t]);
                b[nb][1] = __float_as_uint(Vs[n0 + g][k + t + 4]);
            }
            #pragma unroll
            for (int nb = 0; nb < 8; ++nb)
                mma8(O[nb], a2, b[nb]);
        }
        __syncthreads();      // all warps done with Vs before next iter's V prefetch
    }

    // ── row |S|-sum reduction within quad ──
    #pragma unroll
    for (int rh = 0; rh < 2; ++rh) {
        asum[rh] += __shfl_xor_sync(0xffffffffu, asum[rh], 1);
        asum[rh] += __shfl_xor_sync(0xffffffffu, asum[rh], 2);
    }

    #pragma unroll
    for (int rh = 0; rh < 2; ++rh) {
        float inv = 1.f / asum[rh];
        int l = q0 + wr + g + rh * 8;
        float* op = out + ((size_t)(n * SEQL + l)) * DMODEL + h * HDIM;
        #pragma unroll
        for (int nb = 0; nb < 8; ++nb) {
            int col = nb * 8 + 2 * t;
            float2 st;
            st.x = O[nb][rh * 2 + 0] * inv;
            st.y = O[nb][rh * 2 + 1] * inv;
            *(float2*)(op + col) = st;
        }
    }
}

// ─────────────────────────── launch ─────────────────────────────────────────
extern "C" void kernel_launch(void* const* d_in, const int* in_sizes, int n_in,
                              void* d_out, int out_size)
{
    const float* query = (const float*)d_in[0];
    const float* key   = (const float*)d_in[1];
    const float* Wq    = (const float*)d_in[2];
    const float* Wk    = (const float*)d_in[3];
    const float* Wv    = (const float*)d_in[4];
    const float* coeff = (const float*)d_in[5];
    const float* pw    = (const float*)d_in[6];
    const float* pb    = (const float*)d_in[7];
    float* out = (float*)d_out;

    cudaFuncSetAttribute(proj_tc, cudaFuncAttributeMaxDynamicSharedMemorySize, PJ_SMEM);
    cudaFuncSetAttribute(attn_tc, cudaFuncAttributeMaxDynamicSharedMemorySize, AT_SMEM);

    proj_tc<<<dim3(32, 4, 3), 256, PJ_SMEM>>>(query, key, Wq, Wk, Wv, coeff, pw, pb);
    attn_tc<<<dim3(32, 16), 128, AT_SMEM>>>(out);
}

// round 10
// speedup vs baseline: 1.0906x; 1.0906x over previous
#include <cuda_runtime.h>
#include <math.h>
#include <cstdint>

#define SEQL   2048
#define NHEAD  8
#define DMODEL 512
#define HDIM   64
#define CATD   128
#define NHTOT  16

// Scratch (allocation-free). Values stored pre-rounded to tf32 bit patterns.
__device__ float g_A [(size_t)NHTOT * SEQL * CATD];   // [nh][l][c]   A operand (K-major)
__device__ float g_B [(size_t)NHTOT * SEQL * CATD];   // [nh][l][c]   B operand (K-major)
__device__ float g_Vt[(size_t)NHTOT * HDIM * SEQL];   // [nh][d][l]   stage-2 B operand (K-major)

#define DINL __device__ __forceinline__

DINL uint32_t f2tf(float f) {           // round fp32 -> tf32 (rna), fp32 bit layout
    uint32_t u;
    asm("cvt.rna.tf32.f32 %0, %1;" : "=r"(u) : "f"(f));
    return u;
}

// m16n8k8 tf32 MMA, fp32 accumulate (legacy mma.sync path, base sm_103 ISA)
DINL void mma8(float* d, const uint32_t* a, const uint32_t* b) {
    asm volatile("mma.sync.aligned.m16n8k8.row.col.f32.tf32.tf32.f32 "
        "{%0,%1,%2,%3}, {%4,%5,%6,%7}, {%8,%9}, {%0,%1,%2,%3};"
        : "+f"(d[0]), "+f"(d[1]), "+f"(d[2]), "+f"(d[3])
        : "r"(a[0]), "r"(a[1]), "r"(a[2]), "r"(a[3]), "r"(b[0]), "r"(b[1]));
}

DINL uint32_t smem_u32(const void* p) {
    uint32_t a;
    asm("{ .reg .u64 t; cvta.to.shared.u64 t, %1; cvt.u32.u64 %0, t; }" : "=r"(a) : "l"(p));
    return a;
}
DINL void cp16(uint32_t dst, const void* src) {
    asm volatile("cp.async.cg.shared.global [%0], [%1], 16;" :: "r"(dst), "l"(src));
}
#define CP_COMMIT() asm volatile("cp.async.commit_group;" ::: "memory")
#define CP_WAIT(N)  asm volatile("cp.async.wait_group %0;" :: "n"(N) : "memory")

DINL float softplus_f(float x) {
    return fmaxf(x, 0.f) + log1pf(__expf(-fabsf(x)));
}
DINL void sincos_red(float ang, float* s, float* c) {
    const float INV2PI = 0.15915494309189535f;
    const float PI2_HI = 6.28318548202514648f;
    const float PI2_LO = -1.74845553e-7f;
    float k = rintf(ang * INV2PI);
    float r = fmaf(-k, PI2_HI, ang);
    r = fmaf(-k, PI2_LO, r);
    *s = __sinf(r);
    *c = __cosf(r);
}

// ─────────────────────────── Projection GEMM (tf32 mma.sync) ────────────────
// Unchanged (known-good). C(128x128) = X·W^T over K=512, slabs of 64.
#define PJ_PITCH 68
#define PJ_SMEM  (2 * 128 * PJ_PITCH * 4)

__global__ __launch_bounds__(256, 2) void proj_tc(
    const float* __restrict__ query, const float* __restrict__ key,
    const float* __restrict__ Wq, const float* __restrict__ Wk, const float* __restrict__ Wv,
    const float* __restrict__ coeff, const float* __restrict__ pw, const float* __restrict__ pb)
{
    extern __shared__ float sm[];
    float (*Xs)[PJ_PITCH] = (float(*)[PJ_PITCH])sm;
    float (*Ws)[PJ_PITCH] = (float(*)[PJ_PITCH])(sm + 128 * PJ_PITCH);

    int tid = threadIdx.x, wid = tid >> 5, lane = tid & 31;
    int warpM = wid >> 1, warpN = wid & 1;
    int g = lane >> 2, t = lane & 3;
    int mode = blockIdx.z;
    const float* X = (mode == 0) ? query : key;
    const float* W = (mode == 0) ? Wq : (mode == 1 ? Wk : Wv);
    int m0 = blockIdx.x * 128;
    int c0 = blockIdx.y * 128;

    float acc[2][8][4];
    #pragma unroll
    for (int mb = 0; mb < 2; ++mb)
        #pragma unroll
        for (int nb = 0; nb < 8; ++nb)
            #pragma unroll
            for (int r = 0; r < 4; ++r) acc[mb][nb][r] = 0.f;

    for (int kc = 0; kc < 8; ++kc) {
        __syncthreads();
        #pragma unroll
        for (int it = 0; it < 8; ++it) {
            int idx = it * 256 + tid;
            int r = idx >> 4, c4 = (idx & 15) * 4;
            float4 vx = *(const float4*)(X + (size_t)(m0 + r) * DMODEL + kc * 64 + c4);
            Xs[r][c4 + 0] = __uint_as_float(f2tf(vx.x));
            Xs[r][c4 + 1] = __uint_as_float(f2tf(vx.y));
            Xs[r][c4 + 2] = __uint_as_float(f2tf(vx.z));
            Xs[r][c4 + 3] = __uint_as_float(f2tf(vx.w));
            float4 vw = *(const float4*)(W + (size_t)(c0 + r) * DMODEL + kc * 64 + c4);
            Ws[r][c4 + 0] = __uint_as_float(f2tf(vw.x));
            Ws[r][c4 + 1] = __uint_as_float(f2tf(vw.y));
            Ws[r][c4 + 2] = __uint_as_float(f2tf(vw.z));
            Ws[r][c4 + 3] = __uint_as_float(f2tf(vw.w));
        }
        __syncthreads();

        #pragma unroll
        for (int ks = 0; ks < 8; ++ks) {
            int k = ks * 8;
            uint32_t a[2][4];
            #pragma unroll
            for (int mb = 0; mb < 2; ++mb) {
                int r0 = warpM * 32 + mb * 16;
                a[mb][0] = __float_as_uint(Xs[r0 + g][k + t]);
                a[mb][1] = __float_as_uint(Xs[r0 + g + 8][k + t]);
                a[mb][2] = __float_as_uint(Xs[r0 + g][k + t + 4]);
                a[mb][3] = __float_as_uint(Xs[r0 + g + 8][k + t + 4]);
            }
            uint32_t b[8][2];
            #pragma unroll
            for (int nb = 0; nb < 8; ++nb) {
                int n0 = warpN * 64 + nb * 8;
                b[nb][0] = __float_as_uint(Ws[n0 + g][k + t]);
                b[nb][1] = __float_as_uint(Ws[n0 + g][k + t + 4]);
            }
            #pragma unroll
            for (int mb = 0; mb < 2; ++mb)
                #pragma unroll
                for (int nb = 0; nb < 8; ++nb)
                    mma8(acc[mb][nb], a[mb], b[nb]);
        }
    }

    // epilogue
    #pragma unroll
    for (int mb = 0; mb < 2; ++mb) {
        #pragma unroll
        for (int nb = 0; nb < 8; ++nb) {
            #pragma unroll
            for (int r = 0; r < 4; ++r) {
                int row = warpM * 32 + mb * 16 + g + (r >> 1) * 8;
                int col = warpN * 64 + nb * 8 + 2 * t + (r & 1);
                int m = m0 + row;
                int n = m >> 11, l = m & (SEQL - 1);
                int c = c0 + col;
                int h = c >> 6, dd = c & 63;
                float x = acc[mb][nb][r];
                if (mode == 2) {
                    g_Vt[((size_t)((n * NHEAD + h) * HDIM + dd)) * SEQL + l] =
                        __uint_as_float(f2tf(x));
                } else {
                    size_t base = ((size_t)(n * NHEAD + h) * SEQL + l) * CATD;
                    float w = pw[c];
                    float sn, cs;
                    if (mode == 0) {
                        float sp = softplus_f(x);
                        sincos_red((float)l * w + pb[c], &sn, &cs);
                        g_A[base + dd]      = __uint_as_float(f2tf(sp * cs));
                        g_A[base + 64 + dd] = __uint_as_float(f2tf(sp * sn));
                    } else {
                        float sp = softplus_f(x) * coeff[c];
                        sincos_red((float)l * w, &sn, &cs);
                        g_B[base + dd]      = __uint_as_float(f2tf(sp * cs));
                        g_B[base + 64 + dd] = __uint_as_float(f2tf(sp * sn));
                    }
                }
            }
        }
    }
}

// ─────────────────────────── Attention (tf32 mma.sync, split-group pipeline) ─
// 128 threads, 4 warps, warp tile 16(q) x 64(k). Double-buffered B; V and
// B-prefetch in SEPARATE cp.async groups so each retires independently:
//   top of kt: wait_group 0 -> B(kt) resident (in flight since mid kt-1);
//              barrier; issue V(kt) [grp]; issue B(kt+1)->nxt [grp];
//   mma1 on B[cur] (a-frags in regs); epilogue (warp-private S);
//   wait_group 1 -> V(kt) resident, B(kt+1) STAYS in flight; barrier; mma2.
// 2 barriers/chunk. smem 100KB -> 2 CTAs/SM.
#define AP 132
#define VP 68
#define SP 68
#define F_B0  0
#define F_B1  (64 * AP)                       // 8448
#define F_V   (2 * 64 * AP)                   // 16896
#define F_S   (2 * 64 * AP + 64 * VP)         // 21248
#define AT_SMEM ((2 * 64 * AP + 64 * VP + 4 * 16 * SP) * 4)   // 102400 bytes

__global__ __launch_bounds__(128, 2) void attn_tc(float* __restrict__ out)
{
    extern __shared__ float sm[];
    float (*Vs)[VP] = (float(*)[VP])(sm + F_V);

    int tid = threadIdx.x, wid = tid >> 5, lane = tid & 31;
    int g = lane >> 2, t = lane & 3;
    int wr = wid * 16;                                  // warp's q-row base (local)
    float (*Ssw)[SP] = (float(*)[SP])(sm + F_S + wid * 16 * SP);  // warp-private

    int nh = blockIdx.y;
    int n = nh >> 3, h = nh & 7;
    int qt = (int)gridDim.x - 1 - (int)blockIdx.x;      // heavy tiles first
    int q0 = qt * 64;

    const float* Ab = g_A  + (size_t)nh * SEQL * CATD;
    const float* Bb = g_B  + (size_t)nh * SEQL * CATD;
    const float* Vb = g_Vt + (size_t)nh * HDIM * SEQL;

    uint32_t smu = smem_u32(sm);

    // ── stage A tile (64x128) into B0, pull a-frags to regs ──
    #pragma unroll
    for (int it = 0; it < 16; ++it) {
        int idx = it * 128 + tid;
        int r = idx >> 5, c4 = (idx & 31) * 4;
        cp16(smu + (uint32_t)(F_B0 + r * AP + c4) * 4, Ab + (size_t)(q0 + r) * CATD + c4);
    }
    CP_COMMIT(); CP_WAIT(0);
    __syncthreads();

    uint32_t a[16][4];
    {
        const float (*B0p)[AP] = (const float(*)[AP])(sm + F_B0);
        #pragma unroll
        for (int ks = 0; ks < 16; ++ks) {
            int k = ks * 8;
            a[ks][0] = __float_as_uint(B0p[wr + g][k + t]);
            a[ks][1] = __float_as_uint(B0p[wr + g + 8][k + t]);
            a[ks][2] = __float_as_uint(B0p[wr + g][k + t + 4]);
            a[ks][3] = __float_as_uint(B0p[wr + g + 8][k + t + 4]);
        }
    }
    __syncthreads();          // all warps done reading B0 before B(0) overwrites it

    // ── prologue: B(0) -> B0 (own group) ──
    #pragma unroll
    for (int it = 0; it < 16; ++it) {
        int idx = it * 128 + tid;
        int r = idx >> 5, c4 = (idx & 31) * 4;
        cp16(smu + (uint32_t)(F_B0 + r * AP + c4) * 4, Bb + (size_t)r * CATD + c4);
    }
    CP_COMMIT();

    float O[8][4];
    #pragma unroll
    for (int nb = 0; nb < 8; ++nb)
        #pragma unroll
        for (int r = 0; r < 4; ++r) O[nb][r] = 0.f;
    float asum[2] = {0.f, 0.f};

    for (int kt = 0; kt <= qt; ++kt) {
        int k0 = kt * 64;

        // ── retire B(kt), then issue V(kt) and B(kt+1) as separate groups ──
        CP_WAIT(0);           // only B(kt)'s group is pending here
        __syncthreads();      // B visible to all; prev mma2 done reading Vs

        #pragma unroll
        for (int it = 0; it < 8; ++it) {
            int idx = it * 128 + tid;
            int r = idx >> 4, c4 = (idx & 15) * 4;
            cp16(smu + (uint32_t)(F_V + r * VP + c4) * 4, Vb + (size_t)r * SEQL + k0 + c4);
        }
        CP_COMMIT();          // group: V(kt)
        if (kt < qt) {
            uint32_t bnxt = smu + (uint32_t)(((kt & 1) ? F_B0 : F_B1)) * 4;
            #pragma unroll
            for (int it = 0; it < 16; ++it) {
                int idx = it * 128 + tid;
                int r = idx >> 5, c4 = (idx & 31) * 4;
                cp16(bnxt + (uint32_t)(r * AP + c4) * 4,
                     Bb + (size_t)(k0 + 64 + r) * CATD + c4);
            }
            CP_COMMIT();      // group: B(kt+1) — stays in flight through this chunk
        }

        // ── mma1: S(16x64) = A · B^T over catd=128 (a-frags in regs) ──
        const float (*Bc)[AP] = (const float(*)[AP])(sm + ((kt & 1) ? F_B1 : F_B0));
        float S[8][4];
        #pragma unroll
        for (int nb = 0; nb < 8; ++nb)
            #pragma unroll
            for (int r = 0; r < 4; ++r) S[nb][r] = 0.f;

        #pragma unroll 4
        for (int ks = 0; ks < 16; ++ks) {
            int k = ks * 8;
            uint32_t b[8][2];
            #pragma unroll
            for (int nb = 0; nb < 8; ++nb) {
                int n0 = nb * 8;
                b[nb][0] = __float_as_uint(Bc[n0 + g][k + t]);
                b[nb][1] = __float_as_uint(Bc[n0 + g][k + t + 4]);
            }
            #pragma unroll
            for (int nb = 0; nb < 8; ++nb)
                mma8(S[nb], a[ks], b[nb]);
        }

        // ── epilogue: mask + |S| accumulation + S (tf32) into warp-private Ssw ──
        bool diag = (kt == qt);
        #pragma unroll
        for (int nb = 0; nb < 8; ++nb) {
            int col = nb * 8 + 2 * t;
            #pragma unroll
            for (int rh = 0; rh < 2; ++rh) {
                int rowl = g + rh * 8;
                float v0 = S[nb][rh * 2 + 0];
                float v1 = S[nb][rh * 2 + 1];
                if (diag) {
                    int qg = wr + rowl;
                    if (col + 0 > qg) v0 = 0.f;
                    if (col + 1 > qg) v1 = 0.f;
                }
                asum[rh] += fabsf(v0) + fabsf(v1);
                float2 st;
                st.x = __uint_as_float(f2tf(v0));
                st.y = __uint_as_float(f2tf(v1));
                *(float2*)&Ssw[rowl][col] = st;
            }
        }
        __syncwarp();

        // ── retire V(kt) ONLY (B(kt+1) remains in flight) ──
        if (kt < qt) { CP_WAIT(1); } else { CP_WAIT(0); }
        __syncthreads();

        // ── mma2: O(16x64) += S · Vt^T over 64 keys ──
        #pragma unroll 4
        for (int ks = 0; ks < 8; ++ks) {
            int k = ks * 8;
            uint32_t a2[4];
            a2[0] = __float_as_uint(Ssw[g][k + t]);
            a2[1] = __float_as_uint(Ssw[g + 8][k + t]);
            a2[2] = __float_as_uint(Ssw[g][k + t + 4]);
            a2[3] = __float_as_uint(Ssw[g + 8][k + t + 4]);
            uint32_t b[8][2];
            #pragma unroll
            for (int nb = 0; nb < 8; ++nb) {
                int n0 = nb * 8;
                b[nb][0] = __float_as_uint(Vs[n0 + g][k + t]);
                b[nb][1] = __float_as_uint(Vs[n0 + g][k + t + 4]);
            }
            #pragma unroll
            for (int nb = 0; nb < 8; ++nb)
                mma8(O[nb], a2, b[nb]);
        }
        // no end barrier: next iter's top barrier orders Vs reuse
    }

    // ── row |S|-sum reduction within quad ──
    #pragma unroll
    for (int rh = 0; rh < 2; ++rh) {
        asum[rh] += __shfl_xor_sync(0xffffffffu, asum[rh], 1);
        asum[rh] += __shfl_xor_sync(0xffffffffu, asum[rh], 2);
    }

    #pragma unroll
    for (int rh = 0; rh < 2; ++rh) {
        float inv = 1.f / asum[rh];
        int l = q0 + wr + g + rh * 8;
        float* op = out + ((size_t)(n * SEQL + l)) * DMODEL + h * HDIM;
        #pragma unroll
        for (int nb = 0; nb < 8; ++nb) {
            int col = nb * 8 + 2 * t;
            float2 st;
            st.x = O[nb][rh * 2 + 0] * inv;
            st.y = O[nb][rh * 2 + 1] * inv;
            *(float2*)(op + col) = st;
        }
    }
}

// ─────────────────────────── launch ─────────────────────────────────────────
extern "C" void kernel_launch(void* const* d_in, const int* in_sizes, int n_in,
                              void* d_out, int out_size)
{
    const float* query = (const float*)d_in[0];
    const float* key   = (const float*)d_in[1];
    const float* Wq    = (const float*)d_in[2];
    const float* Wk    = (const float*)d_in[3];
    const float* Wv    = (const float*)d_in[4];
    const float* coeff = (const float*)d_in[5];
    const float* pw    = (const float*)d_in[6];
    const float* pb    = (const float*)d_in[7];
    float* out = (float*)d_out;

    cudaFuncSetAttribute(proj_tc, cudaFuncAttributeMaxDynamicSharedMemorySize, PJ_SMEM);
    cudaFuncSetAttribute(attn_tc, cudaFuncAttributeMaxDynamicSharedMemorySize, AT_SMEM);

    proj_tc<<<dim3(32, 4, 3), 256, PJ_SMEM>>>(query, key, Wq, Wk, Wv, coeff, pw, pb);
    attn_tc<<<dim3(32, 16), 128, AT_SMEM>>>(out);
}

// round 11
// speedup vs baseline: 1.1072x; 1.0152x over previous
#include <cuda_runtime.h>
#include <math.h>
#include <cstdint>

#define SEQL   2048
#define NHEAD  8
#define DMODEL 512
#define HDIM   64
#define CATD   128
#define NHTOT  16
#define XTOT   (4096 * DMODEL)     // one input tensor (N*L=4096 rows x 512)

// Scratch (allocation-free). All values stored pre-rounded to tf32 bit patterns.
__device__ float g_A [(size_t)NHTOT * SEQL * CATD];   // [nh][l][c]   attn A operand
__device__ float g_B [(size_t)NHTOT * SEQL * CATD];   // [nh][l][c]   attn B operand
__device__ float g_Vt[(size_t)NHTOT * HDIM * SEQL];   // [nh][d][l]   attn stage-2 B operand
__device__ float g_Xr[2 * XTOT];                      // tf32-rounded query | key
__device__ float g_Wr[3 * DMODEL * DMODEL];           // tf32-rounded Wq | Wk | Wv

#define DINL __device__ __forceinline__

DINL uint32_t f2tf(float f) {           // round fp32 -> tf32 (rna), fp32 bit layout
    uint32_t u;
    asm("cvt.rna.tf32.f32 %0, %1;" : "=r"(u) : "f"(f));
    return u;
}

// m16n8k8 tf32 MMA, fp32 accumulate (legacy mma.sync path, base sm_103 ISA)
DINL void mma8(float* d, const uint32_t* a, const uint32_t* b) {
    asm volatile("mma.sync.aligned.m16n8k8.row.col.f32.tf32.tf32.f32 "
        "{%0,%1,%2,%3}, {%4,%5,%6,%7}, {%8,%9}, {%0,%1,%2,%3};"
        : "+f"(d[0]), "+f"(d[1]), "+f"(d[2]), "+f"(d[3])
        : "r"(a[0]), "r"(a[1]), "r"(a[2]), "r"(a[3]), "r"(b[0]), "r"(b[1]));
}

DINL uint32_t smem_u32(const void* p) {
    uint32_t a;
    asm("{ .reg .u64 t; cvta.to.shared.u64 t, %1; cvt.u32.u64 %0, t; }" : "=r"(a) : "l"(p));
    return a;
}
DINL void cp16(uint32_t dst, const void* src) {
    asm volatile("cp.async.cg.shared.global [%0], [%1], 16;" :: "r"(dst), "l"(src));
}
#define CP_COMMIT() asm volatile("cp.async.commit_group;" ::: "memory")
#define CP_WAIT0()  asm volatile("cp.async.commit_group;\n\tcp.async.wait_group 0;" ::: "memory")

DINL float softplus_f(float x) {
    return fmaxf(x, 0.f) + log1pf(__expf(-fabsf(x)));
}
DINL void sincos_red(float ang, float* s, float* c) {
    const float INV2PI = 0.15915494309189535f;
    const float PI2_HI = 6.28318548202514648f;
    const float PI2_LO = -1.74845553e-7f;
    float k = rintf(ang * INV2PI);
    float r = fmaf(-k, PI2_HI, ang);
    r = fmaf(-k, PI2_LO, r);
    *s = __sinf(r);
    *c = __cosf(r);
}

// ─────────────────────────── Prepass: tf32-round inputs into scratch ────────
__global__ __launch_bounds__(256) void prepass_tc(
    const float* __restrict__ query, const float* __restrict__ key,
    const float* __restrict__ Wq, const float* __restrict__ Wk, const float* __restrict__ Wv)
{
    const int nX = XTOT / 4;                 // float4 count per input tensor
    const int nW = DMODEL * DMODEL / 4;      // float4 count per weight
    const int total = 2 * nX + 3 * nW;
    for (int i = blockIdx.x * blockDim.x + threadIdx.x; i < total;
         i += gridDim.x * blockDim.x) {
        const float4* src;
        float4* dst;
        int j;
        if (i < nX) {
            src = (const float4*)query; dst = (float4*)g_Xr; j = i;
        } else if (i < 2 * nX) {
            src = (const float4*)key;   dst = (float4*)(g_Xr + XTOT); j = i - nX;
        } else {
            int wi = i - 2 * nX;
            int ws = wi / nW; j = wi - ws * nW;
            src = (ws == 0) ? (const float4*)Wq : (ws == 1) ? (const float4*)Wk
                                                            : (const float4*)Wv;
            dst = (float4*)(g_Wr + (size_t)ws * DMODEL * DMODEL);
        }
        float4 v = src[j];
        v.x = __uint_as_float(f2tf(v.x));
        v.y = __uint_as_float(f2tf(v.y));
        v.z = __uint_as_float(f2tf(v.z));
        v.w = __uint_as_float(f2tf(v.w));
        dst[j] = v;
    }
}

// ─────────────────────────── Projection GEMM (tf32 mma.sync, cp.async) ──────
// C(128x128) = X·W^T over K=512, slabs of 64. Staging is raw cp.async from
// pre-rounded scratch (no f2tf/STS/LDG round-trip). 8 warps: 4(M) x 2(N).
#define PJ_PITCH 68
#define PJ_SMEM  (2 * 128 * PJ_PITCH * 4)

__global__ __launch_bounds__(256, 2) void proj_tc(
    const float* __restrict__ coeff, const float* __restrict__ pw, const float* __restrict__ pb)
{
    extern __shared__ float sm[];
    float (*Xs)[PJ_PITCH] = (float(*)[PJ_PITCH])sm;
    float (*Ws)[PJ_PITCH] = (float(*)[PJ_PITCH])(sm + 128 * PJ_PITCH);

    int tid = threadIdx.x, wid = tid >> 5, lane = tid & 31;
    int warpM = wid >> 1, warpN = wid & 1;
    int g = lane >> 2, t = lane & 3;
    int mode = blockIdx.z;
    const float* X = g_Xr + (mode == 0 ? 0 : XTOT);
    const float* W = g_Wr + (size_t)mode * DMODEL * DMODEL;
    int m0 = blockIdx.x * 128;
    int c0 = blockIdx.y * 128;

    uint32_t xs_u = smem_u32(sm);
    uint32_t ws_u = xs_u + 128 * PJ_PITCH * 4;

    float acc[2][8][4];
    #pragma unroll
    for (int mb = 0; mb < 2; ++mb)
        #pragma unroll
        for (int nb = 0; nb < 8; ++nb)
            #pragma unroll
            for (int r = 0; r < 4; ++r) acc[mb][nb][r] = 0.f;

    for (int kc = 0; kc < 8; ++kc) {
        __syncthreads();
        #pragma unroll
        for (int it = 0; it < 8; ++it) {
            int idx = it * 256 + tid;
            int r = idx >> 4, c4 = (idx & 15) * 4;
            cp16(xs_u + (uint32_t)(r * PJ_PITCH + c4) * 4,
                 X + (size_t)(m0 + r) * DMODEL + kc * 64 + c4);
            cp16(ws_u + (uint32_t)(r * PJ_PITCH + c4) * 4,
                 W + (size_t)(c0 + r) * DMODEL + kc * 64 + c4);
        }
        CP_WAIT0();
        __syncthreads();

        #pragma unroll
        for (int ks = 0; ks < 8; ++ks) {
            int k = ks * 8;
            uint32_t a[2][4];
            #pragma unroll
            for (int mb = 0; mb < 2; ++mb) {
                int r0 = warpM * 32 + mb * 16;
                a[mb][0] = __float_as_uint(Xs[r0 + g][k + t]);
                a[mb][1] = __float_as_uint(Xs[r0 + g + 8][k + t]);
                a[mb][2] = __float_as_uint(Xs[r0 + g][k + t + 4]);
                a[mb][3] = __float_as_uint(Xs[r0 + g + 8][k + t + 4]);
            }
            uint32_t b[8][2];
            #pragma unroll
            for (int nb = 0; nb < 8; ++nb) {
                int n0 = warpN * 64 + nb * 8;
                b[nb][0] = __float_as_uint(Ws[n0 + g][k + t]);
                b[nb][1] = __float_as_uint(Ws[n0 + g][k + t + 4]);
            }
            #pragma unroll
            for (int mb = 0; mb < 2; ++mb)
                #pragma unroll
                for (int nb = 0; nb < 8; ++nb)
                    mma8(acc[mb][nb], a[mb], b[nb]);
        }
    }

    // epilogue (unchanged numerics)
    #pragma unroll
    for (int mb = 0; mb < 2; ++mb) {
        #pragma unroll
        for (int nb = 0; nb < 8; ++nb) {
            #pragma unroll
            for (int r = 0; r < 4; ++r) {
                int row = warpM * 32 + mb * 16 + g + (r >> 1) * 8;
                int col = warpN * 64 + nb * 8 + 2 * t + (r & 1);
                int m = m0 + row;
                int n = m >> 11, l = m & (SEQL - 1);
                int c = c0 + col;
                int h = c >> 6, dd = c & 63;
                float x = acc[mb][nb][r];
                if (mode == 2) {
                    g_Vt[((size_t)((n * NHEAD + h) * HDIM + dd)) * SEQL + l] =
                        __uint_as_float(f2tf(x));
                } else {
                    size_t base = ((size_t)(n * NHEAD + h) * SEQL + l) * CATD;
                    float w = pw[c];
                    float sn, cs;
                    if (mode == 0) {
                        float sp = softplus_f(x);
                        sincos_red((float)l * w + pb[c], &sn, &cs);
                        g_A[base + dd]      = __uint_as_float(f2tf(sp * cs));
                        g_A[base + 64 + dd] = __uint_as_float(f2tf(sp * sn));
                    } else {
                        float sp = softplus_f(x) * coeff[c];
                        sincos_red((float)l * w, &sn, &cs);
                        g_B[base + dd]      = __uint_as_float(f2tf(sp * cs));
                        g_B[base + 64 + dd] = __uint_as_float(f2tf(sp * sn));
                    }
                }
            }
        }
    }
}

// ─────────────────────────── Attention (tf32 mma.sync — R7 best config) ─────
// 128 threads, 4 warps, warp tile 16(q) x 64(k), A-frags resident in regs,
// warp-private S buffer, cp.async staging. 67KB smem -> 3 CTAs/SM.
#define AP 132
#define VP 68
#define SP 68
#define AT_BS_F   0
#define AT_VS_F   (64 * AP)                 // 8448
#define AT_SS_F   (64 * AP + 64 * VP)       // 12800
#define AT_SMEM   ((64 * AP + 64 * VP + 4 * 16 * SP) * 4)   // 68608 bytes

__global__ __launch_bounds__(128, 3) void attn_tc(float* __restrict__ out)
{
    extern __shared__ float sm[];
    float (*Bs)[AP] = (float(*)[AP])(sm + AT_BS_F);
    float (*Vs)[VP] = (float(*)[VP])(sm + AT_VS_F);

    int tid = threadIdx.x, wid = tid >> 5, lane = tid & 31;
    int g = lane >> 2, t = lane & 3;
    int wr = wid * 16;                                  // warp's q-row base (local)
    float (*Ssw)[SP] = (float(*)[SP])(sm + AT_SS_F + wid * 16 * SP);  // warp-private

    int nh = blockIdx.y;
    int n = nh >> 3, h = nh & 7;
    int qt = (int)gridDim.x - 1 - (int)blockIdx.x;      // heavy tiles first
    int q0 = qt * 64;

    const float* Ab = g_A  + (size_t)nh * SEQL * CATD;
    const float* Bb = g_B  + (size_t)nh * SEQL * CATD;
    const float* Vb = g_Vt + (size_t)nh * HDIM * SEQL;

    uint32_t bs_u = smem_u32(sm);

    // ── one-time: stage A tile (64x128) into Bs region, pull a-frags to regs ──
    #pragma unroll
    for (int it = 0; it < 16; ++it) {
        int idx = it * 128 + tid;
        int r = idx >> 5, c4 = (idx & 31) * 4;
        cp16(bs_u + (uint32_t)(r * AP + c4) * 4, Ab + (size_t)(q0 + r) * CATD + c4);
    }
    CP_WAIT0();
    __syncthreads();

    uint32_t a[16][4];
    #pragma unroll
    for (int ks = 0; ks < 16; ++ks) {
        int k = ks * 8;
        a[ks][0] = __float_as_uint(Bs[wr + g][k + t]);
        a[ks][1] = __float_as_uint(Bs[wr + g + 8][k + t]);
        a[ks][2] = __float_as_uint(Bs[wr + g][k + t + 4]);
        a[ks][3] = __float_as_uint(Bs[wr + g + 8][k + t + 4]);
    }

    float O[8][4];
    #pragma unroll
    for (int nb = 0; nb < 8; ++nb)
        #pragma unroll
        for (int r = 0; r < 4; ++r) O[nb][r] = 0.f;
    float asum[2] = {0.f, 0.f};

    for (int kt = 0; kt <= qt; ++kt) {
        int k0 = kt * 64;
        __syncthreads();   // prior mma1/mma2 (and a-frag pulls, iter 0) done with Bs/Vs

        // ── stage B chunk (64x128) + V chunk (64x64) via cp.async ──
        #pragma unroll
        for (int it = 0; it < 16; ++it) {
            int idx = it * 128 + tid;
            int r = idx >> 5, c4 = (idx & 31) * 4;
            cp16(bs_u + (uint32_t)(r * AP + c4) * 4, Bb + (size_t)(k0 + r) * CATD + c4);
        }
        #pragma unroll
        for (int it = 0; it < 8; ++it) {
            int idx = it * 128 + tid;
            int r = idx >> 4, c4 = (idx & 15) * 4;
            cp16(bs_u + (uint32_t)(AT_VS_F + r * VP + c4) * 4,
                 Vb + (size_t)r * SEQL + k0 + c4);
        }
        CP_WAIT0();
        __syncthreads();

        // ── mma1: S(16x64) = A · B^T over catd=128 (a-frags from registers) ──
        float S[8][4];
        #pragma unroll
        for (int nb = 0; nb < 8; ++nb)
            #pragma unroll
            for (int r = 0; r < 4; ++r) S[nb][r] = 0.f;

        #pragma unroll 4
        for (int ks = 0; ks < 16; ++ks) {
            int k = ks * 8;
            uint32_t b[8][2];
            #pragma unroll
            for (int nb = 0; nb < 8; ++nb) {
                int n0 = nb * 8;
                b[nb][0] = __float_as_uint(Bs[n0 + g][k + t]);
                b[nb][1] = __float_as_uint(Bs[n0 + g][k + t + 4]);
            }
            #pragma unroll
            for (int nb = 0; nb < 8; ++nb)
                mma8(S[nb], a[ks], b[nb]);
        }

        // ── epilogue: mask + |S| accumulation + S (tf32) into warp-private Ssw ──
        bool diag = (kt == qt);
        #pragma unroll
        for (int nb = 0; nb < 8; ++nb) {
            int col = nb * 8 + 2 * t;                   // local key col
            #pragma unroll
            for (int rh = 0; rh < 2; ++rh) {
                int rowl = g + rh * 8;                  // local row within warp tile
                float v0 = S[nb][rh * 2 + 0];
                float v1 = S[nb][rh * 2 + 1];
                if (diag) {
                    int qg = wr + rowl;                 // local q (k0 == q0 base)
                    if (col + 0 > qg) v0 = 0.f;
                    if (col + 1 > qg) v1 = 0.f;
                }
                asum[rh] += fabsf(v0) + fabsf(v1);
                float2 st;
                st.x = __uint_as_float(f2tf(v0));
                st.y = __uint_as_float(f2tf(v1));
                *(float2*)&Ssw[rowl][col] = st;
            }
        }
        __syncwarp();                                   // warp-private Ssw -> no CTA barrier

        // ── mma2: O(16x64) += S · Vt^T over 64 keys ──
        #pragma unroll 4
        for (int ks = 0; ks < 8; ++ks) {
            int k = ks * 8;
            uint32_t a2[4];
            a2[0] = __float_as_uint(Ssw[g][k + t]);
            a2[1] = __float_as_uint(Ssw[g + 8][k + t]);
            a2[2] = __float_as_uint(Ssw[g][k + t + 4]);
            a2[3] = __float_as_uint(Ssw[g + 8][k + t + 4]);
            uint32_t b[8][2];
            #pragma unroll
            for (int nb = 0; nb < 8; ++nb) {
                int n0 = nb * 8;
                b[nb][0] = __float_as_uint(Vs[n0 + g][k + t]);
                b[nb][1] = __float_as_uint(Vs[n0 + g][k + t + 4]);
            }
            #pragma unroll
            for (int nb = 0; nb < 8; ++nb)
                mma8(O[nb], a2, b[nb]);
        }
    }

    // ── row |S|-sum reduction within quad (lanes share rows across t) ──
    #pragma unroll
    for (int rh = 0; rh < 2; ++rh) {
        asum[rh] += __shfl_xor_sync(0xffffffffu, asum[rh], 1);
        asum[rh] += __shfl_xor_sync(0xffffffffu, asum[rh], 2);
    }

    #pragma unroll
    for (int rh = 0; rh < 2; ++rh) {
        float inv = 1.f / asum[rh];
        int l = q0 + wr + g + rh * 8;
        float* op = out + ((size_t)(n * SEQL + l)) * DMODEL + h * HDIM;
        #pragma unroll
        for (int nb = 0; nb < 8; ++nb) {
            int col = nb * 8 + 2 * t;
            float2 st;
            st.x = O[nb][rh * 2 + 0] * inv;
            st.y = O[nb][rh * 2 + 1] * inv;
            *(float2*)(op + col) = st;
        }
    }
}

// ─────────────────────────── launch ─────────────────────────────────────────
extern "C" void kernel_launch(void* const* d_in, const int* in_sizes, int n_in,
                              void* d_out, int out_size)
{
    const float* query = (const float*)d_in[0];
    const float* key   = (const float*)d_in[1];
    const float* Wq    = (const float*)d_in[2];
    const float* Wk    = (const float*)d_in[3];
    const float* Wv    = (const float*)d_in[4];
    const float* coeff = (const float*)d_in[5];
    const float* pw    = (const float*)d_in[6];
    const float* pb    = (const float*)d_in[7];
    float* out = (float*)d_out;

    cudaFuncSetAttribute(proj_tc, cudaFuncAttributeMaxDynamicSharedMemorySize, PJ_SMEM);
    cudaFuncSetAttribute(attn_tc, cudaFuncAttributeMaxDynamicSharedMemorySize, AT_SMEM);

    prepass_tc<<<1024, 256>>>(query, key, Wq, Wk, Wv);
    proj_tc<<<dim3(32, 4, 3), 256, PJ_SMEM>>>(coeff, pw, pb);
    attn_tc<<<dim3(32, 16), 128, AT_SMEM>>>(out);
}

// round 13
// speedup vs baseline: 1.1367x; 1.0267x over previous
#include <cuda_runtime.h>
#include <math.h>
#include <cstdint>

#define SEQL   2048
#define NHEAD  8
#define DMODEL 512
#define HDIM   64
#define CATD   128
#define NHTOT  16
#define XTOT   (4096 * DMODEL)     // one input tensor (N*L=4096 rows x 512)

// Scratch (allocation-free). All values stored pre-rounded to tf32 bit patterns.
__device__ float g_A [(size_t)NHTOT * SEQL * CATD];   // [nh][l][c]   attn A operand
__device__ float g_B [(size_t)NHTOT * SEQL * CATD];   // [nh][l][c]   attn B operand
__device__ float g_Vt[(size_t)NHTOT * HDIM * SEQL];   // [nh][d][l]   attn stage-2 B operand
__device__ float g_Xr[2 * XTOT];                      // tf32-rounded query | key
__device__ float g_Wr[3 * DMODEL * DMODEL];           // tf32-rounded Wq | Wk | Wv

#define DINL __device__ __forceinline__

DINL uint32_t f2tf(float f) {           // round fp32 -> tf32 (rna), fp32 bit layout
    uint32_t u;
    asm("cvt.rna.tf32.f32 %0, %1;" : "=r"(u) : "f"(f));
    return u;
}

// m16n8k8 tf32 MMA, fp32 accumulate (legacy mma.sync path, base sm_103 ISA)
DINL void mma8(float* d, const uint32_t* a, const uint32_t* b) {
    asm volatile("mma.sync.aligned.m16n8k8.row.col.f32.tf32.tf32.f32 "
        "{%0,%1,%2,%3}, {%4,%5,%6,%7}, {%8,%9}, {%0,%1,%2,%3};"
        : "+f"(d[0]), "+f"(d[1]), "+f"(d[2]), "+f"(d[3])
        : "r"(a[0]), "r"(a[1]), "r"(a[2]), "r"(a[3]), "r"(b[0]), "r"(b[1]));
}

DINL uint32_t smem_u32(const void* p) {
    uint32_t a;
    asm("{ .reg .u64 t; cvta.to.shared.u64 t, %1; cvt.u32.u64 %0, t; }" : "=r"(a) : "l"(p));
    return a;
}
DINL void cp16(uint32_t dst, const void* src) {
    asm volatile("cp.async.cg.shared.global [%0], [%1], 16;" :: "r"(dst), "l"(src));
}
#define CP_COMMIT() asm volatile("cp.async.commit_group;" ::: "memory")
#define CP_WAIT(N)  asm volatile("cp.async.wait_group %0;" :: "n"(N) : "memory")
#define CP_WAIT0()  asm volatile("cp.async.commit_group;\n\tcp.async.wait_group 0;" ::: "memory")

DINL float softplus_f(float x) {
    return fmaxf(x, 0.f) + log1pf(__expf(-fabsf(x)));
}
DINL void sincos_red(float ang, float* s, float* c) {
    const float INV2PI = 0.15915494309189535f;
    const float PI2_HI = 6.28318548202514648f;
    const float PI2_LO = -1.74845553e-7f;
    float k = rintf(ang * INV2PI);
    float r = fmaf(-k, PI2_HI, ang);
    r = fmaf(-k, PI2_LO, r);
    *s = __sinf(r);
    *c = __cosf(r);
}

// ─────────────────────────── Prepass: tf32-round inputs into scratch ────────
// blockIdx.y selects the tensor (branch once, not per element).
__global__ __launch_bounds__(256) void prepass_tc(
    const float* __restrict__ query, const float* __restrict__ key,
    const float* __restrict__ Wq, const float* __restrict__ Wk, const float* __restrict__ Wv)
{
    int sel = blockIdx.y;
    const float4* src;
    float4* dst;
    int cnt;
    if (sel == 0)      { src = (const float4*)query; dst = (float4*)g_Xr;          cnt = XTOT / 4; }
    else if (sel == 1) { src = (const float4*)key;   dst = (float4*)(g_Xr + XTOT); cnt = XTOT / 4; }
    else {
        int ws = sel - 2;
        src = (ws == 0) ? (const float4*)Wq : (ws == 1) ? (const float4*)Wk : (const float4*)Wv;
        dst = (float4*)(g_Wr + (size_t)ws * DMODEL * DMODEL);
        cnt = DMODEL * DMODEL / 4;
    }
    for (int i = blockIdx.x * blockDim.x + threadIdx.x; i < cnt; i += gridDim.x * blockDim.x) {
        float4 v = src[i];
        v.x = __uint_as_float(f2tf(v.x));
        v.y = __uint_as_float(f2tf(v.y));
        v.z = __uint_as_float(f2tf(v.z));
        v.w = __uint_as_float(f2tf(v.w));
        dst[i] = v;
    }
}

// ─────────────────────────── Projection GEMM (tf32 mma.sync, dbl-buffered) ──
// C(128x128) = X·W^T over K=512 in 16 slabs of K=32, double-buffered cp.async
// prefetch: slab s+1 loads while slab s computes. 73.7KB smem -> 2 CTAs/SM.
// 8 warps: 4(M) x 2(N), warp tile 32x64. Accumulation k-order identical to R7.
#define PJ_PITCH 36
#define PJ_SLABF (128 * PJ_PITCH)            // floats per (X or W) buffer
#define PJ_SMEM  (4 * PJ_SLABF * 4)          // 73728 bytes: X0|W0|X1|W1

DINL void pj_stage(uint32_t smu, const float* X, const float* W,
                   int m0, int c0, int s, int b, int tid)
{
    uint32_t xo = smu + (uint32_t)(2 * b * PJ_SLABF) * 4;
    uint32_t wo = xo + (uint32_t)PJ_SLABF * 4;
    #pragma unroll
    for (int it = 0; it < 4; ++it) {
        int idx = it * 256 + tid;
        int r = idx >> 3, c4 = (idx & 7) * 4;
        cp16(xo + (uint32_t)(r * PJ_PITCH + c4) * 4,
             X + (size_t)(m0 + r) * DMODEL + s * 32 + c4);
        cp16(wo + (uint32_t)(r * PJ_PITCH + c4) * 4,
             W + (size_t)(c0 + r) * DMODEL + s * 32 + c4);
    }
}

__global__ __launch_bounds__(256, 2) void proj_tc(
    const float* __restrict__ coeff, const float* __restrict__ pw, const float* __restrict__ pb)
{
    extern __shared__ float sm[];

    int tid = threadIdx.x, wid = tid >> 5, lane = tid & 31;
    int warpM = wid >> 1, warpN = wid & 1;
    int g = lane >> 2, t = lane & 3;
    int mode = blockIdx.z;
    const float* X = g_Xr + (mode == 0 ? 0 : XTOT);
    const float* W = g_Wr + (size_t)mode * DMODEL * DMODEL;
    int m0 = blockIdx.x * 128;
    int c0 = blockIdx.y * 128;
    uint32_t smu = smem_u32(sm);

    float acc[2][8][4];
    #pragma unroll
    for (int mb = 0; mb < 2; ++mb)
        #pragma unroll
        for (int nb = 0; nb < 8; ++nb)
            #pragma unroll
            for (int r = 0; r < 4; ++r) acc[mb][nb][r] = 0.f;

    pj_stage(smu, X, W, m0, c0, 0, 0, tid);
    CP_COMMIT();

    for (int s = 0; s < 16; ++s) {
        int cur = s & 1;
        if (s < 15) {
            pj_stage(smu, X, W, m0, c0, s + 1, cur ^ 1, tid);
            CP_COMMIT();
            CP_WAIT(1);       // slab s resident; slab s+1 stays in flight
        } else {
            CP_WAIT(0);
        }
        __syncthreads();      // slab s visible to all warps

        const float (*Xs)[PJ_PITCH] = (const float(*)[PJ_PITCH])(sm + 2 * cur * PJ_SLABF);
        const float (*Ws)[PJ_PITCH] = (const float(*)[PJ_PITCH])(sm + (2 * cur + 1) * PJ_SLABF);

        #pragma unroll
        for (int ks = 0; ks < 4; ++ks) {
            int k = ks * 8;
            uint32_t a[2][4];
            #pragma unroll
            for (int mb = 0; mb < 2; ++mb) {
                int r0 = warpM * 32 + mb * 16;
                a[mb][0] = __float_as_uint(Xs[r0 + g][k + t]);
                a[mb][1] = __float_as_uint(Xs[r0 + g + 8][k + t]);
                a[mb][2] = __float_as_uint(Xs[r0 + g][k + t + 4]);
                a[mb][3] = __float_as_uint(Xs[r0 + g + 8][k + t + 4]);
            }
            uint32_t b[8][2];
            #pragma unroll
            for (int nb = 0; nb < 8; ++nb) {
                int n0 = warpN * 64 + nb * 8;
                b[nb][0] = __float_as_uint(Ws[n0 + g][k + t]);
                b[nb][1] = __float_as_uint(Ws[n0 + g][k + t + 4]);
            }
            #pragma unroll
            for (int mb = 0; mb < 2; ++mb)
                #pragma unroll
                for (int nb = 0; nb < 8; ++nb)
                    mma8(acc[mb][nb], a[mb], b[nb]);
        }
        __syncthreads();      // all warps done with buf[cur] before iter s+1 overwrites it
    }

    // epilogue (unchanged numerics)
    #pragma unroll
    for (int mb = 0; mb < 2; ++mb) {
        #pragma unroll
        for (int nb = 0; nb < 8; ++nb) {
            #pragma unroll
            for (int r = 0; r < 4; ++r) {
                int row = warpM * 32 + mb * 16 + g + (r >> 1) * 8;
                int col = warpN * 64 + nb * 8 + 2 * t + (r & 1);
                int m = m0 + row;
                int n = m >> 11, l = m & (SEQL - 1);
                int c = c0 + col;
                int h = c >> 6, dd = c & 63;
                float x = acc[mb][nb][r];
                if (mode == 2) {
                    g_Vt[((size_t)((n * NHEAD + h) * HDIM + dd)) * SEQL + l] =
                        __uint_as_float(f2tf(x));
                } else {
                    size_t base = ((size_t)(n * NHEAD + h) * SEQL + l) * CATD;
                    float w = pw[c];
                    float sn, cs;
                    if (mode == 0) {
                        float sp = softplus_f(x);
                        sincos_red((float)l * w + pb[c], &sn, &cs);
                        g_A[base + dd]      = __uint_as_float(f2tf(sp * cs));
                        g_A[base + 64 + dd] = __uint_as_float(f2tf(sp * sn));
                    } else {
                        float sp = softplus_f(x) * coeff[c];
                        sincos_red((float)l * w, &sn, &cs);
                        g_B[base + dd]      = __uint_as_float(f2tf(sp * cs));
                        g_B[base + 64 + dd] = __uint_as_float(f2tf(sp * sn));
                    }
                }
            }
        }
    }
}

// ─────────────────────────── Attention (tf32 mma.sync — R7 best config) ─────
// 128 threads, 4 warps, warp tile 16(q) x 64(k), A-frags resident in regs,
// warp-private S buffer, cp.async staging. 67KB smem -> 3 CTAs/SM.
#define AP 132
#define VP 68
#define SP 68
#define AT_BS_F   0
#define AT_VS_F   (64 * AP)                 // 8448
#define AT_SS_F   (64 * AP + 64 * VP)       // 12800
#define AT_SMEM   ((64 * AP + 64 * VP + 4 * 16 * SP) * 4)   // 68608 bytes

__global__ __launch_bounds__(128, 3) void attn_tc(float* __restrict__ out)
{
    extern __shared__ float sm[];
    float (*Bs)[AP] = (float(*)[AP])(sm + AT_BS_F);
    float (*Vs)[VP] = (float(*)[VP])(sm + AT_VS_F);

    int tid = threadIdx.x, wid = tid >> 5, lane = tid & 31;
    int g = lane >> 2, t = lane & 3;
    int wr = wid * 16;                                  // warp's q-row base (local)
    float (*Ssw)[SP] = (float(*)[SP])(sm + AT_SS_F + wid * 16 * SP);  // warp-private

    int nh = blockIdx.y;
    int n = nh >> 3, h = nh & 7;
    int qt = (int)gridDim.x - 1 - (int)blockIdx.x;      // heavy tiles first
    int q0 = qt * 64;

    const float* Ab = g_A  + (size_t)nh * SEQL * CATD;
    const float* Bb = g_B  + (size_t)nh * SEQL * CATD;
    const float* Vb = g_Vt + (size_t)nh * HDIM * SEQL;

    uint32_t bs_u = smem_u32(sm);

    // ── one-time: stage A tile (64x128) into Bs region, pull a-frags to regs ──
    #pragma unroll
    for (int it = 0; it < 16; ++it) {
        int idx = it * 128 + tid;
        int r = idx >> 5, c4 = (idx & 31) * 4;
        cp16(bs_u + (uint32_t)(r * AP + c4) * 4, Ab + (size_t)(q0 + r) * CATD + c4);
    }
    CP_WAIT0();
    __syncthreads();

    uint32_t a[16][4];
    #pragma unroll
    for (int ks = 0; ks < 16; ++ks) {
        int k = ks * 8;
        a[ks][0] = __float_as_uint(Bs[wr + g][k + t]);
        a[ks][1] = __float_as_uint(Bs[wr + g + 8][k + t]);
        a[ks][2] = __float_as_uint(Bs[wr + g][k + t + 4]);
        a[ks][3] = __float_as_uint(Bs[wr + g + 8][k + t + 4]);
    }

    float O[8][4];
    #pragma unroll
    for (int nb = 0; nb < 8; ++nb)
        #pragma unroll
        for (int r = 0; r < 4; ++r) O[nb][r] = 0.f;
    float asum[2] = {0.f, 0.f};

    for (int kt = 0; kt <= qt; ++kt) {
        int k0 = kt * 64;
        __syncthreads();   // prior mma1/mma2 (and a-frag pulls, iter 0) done with Bs/Vs

        // ── stage B chunk (64x128) + V chunk (64x64) via cp.async ──
        #pragma unroll
        for (int it = 0; it < 16; ++it) {
            int idx = it * 128 + tid;
            int r = idx >> 5, c4 = (idx & 31) * 4;
            cp16(bs_u + (uint32_t)(r * AP + c4) * 4, Bb + (size_t)(k0 + r) * CATD + c4);
        }
        #pragma unroll
        for (int it = 0; it < 8; ++it) {
            int idx = it * 128 + tid;
            int r = idx >> 4, c4 = (idx & 15) * 4;
            cp16(bs_u + (uint32_t)(AT_VS_F + r * VP + c4) * 4,
                 Vb + (size_t)r * SEQL + k0 + c4);
        }
        CP_WAIT0();
        __syncthreads();

        // ── mma1: S(16x64) = A · B^T over catd=128 (a-frags from registers) ──
        float S[8][4];
        #pragma unroll
        for (int nb = 0; nb < 8; ++nb)
            #pragma unroll
            for (int r = 0; r < 4; ++r) S[nb][r] = 0.f;

        #pragma unroll 4
        for (int ks = 0; ks < 16; ++ks) {
            int k = ks * 8;
            uint32_t b[8][2];
            #pragma unroll
            for (int nb = 0; nb < 8; ++nb) {
                int n0 = nb * 8;
                b[nb][0] = __float_as_uint(Bs[n0 + g][k + t]);
                b[nb][1] = __float_as_uint(Bs[n0 + g][k + t + 4]);
            }
            #pragma unroll
            for (int nb = 0; nb < 8; ++nb)
                mma8(S[nb], a[ks], b[nb]);
        }

        // ── epilogue: mask + |S| accumulation + S (tf32) into warp-private Ssw ──
        bool diag = (kt == qt);
        #pragma unroll
        for (int nb = 0; nb < 8; ++nb) {
            int col = nb * 8 + 2 * t;                   // local key col
            #pragma unroll
            for (int rh = 0; rh < 2; ++rh) {
                int rowl = g + rh * 8;                  // local row within warp tile
                float v0 = S[nb][rh * 2 + 0];
                float v1 = S[nb][rh * 2 + 1];
                if (diag) {
                    int qg = wr + rowl;                 // local q (k0 == q0 base)
                    if (col + 0 > qg) v0 = 0.f;
                    if (col + 1 > qg) v1 = 0.f;
                }
                asum[rh] += fabsf(v0) + fabsf(v1);
                float2 st;
                st.x = __uint_as_float(f2tf(v0));
                st.y = __uint_as_float(f2tf(v1));
                *(float2*)&Ssw[rowl][col] = st;
            }
        }
        __syncwarp();                                   // warp-private Ssw -> no CTA barrier

        // ── mma2: O(16x64) += S · Vt^T over 64 keys ──
        #pragma unroll 4
        for (int ks = 0; ks < 8; ++ks) {
            int k = ks * 8;
            uint32_t a2[4];
            a2[0] = __float_as_uint(Ssw[g][k + t]);
            a2[1] = __float_as_uint(Ssw[g + 8][k + t]);
            a2[2] = __float_as_uint(Ssw[g][k + t + 4]);
            a2[3] = __float_as_uint(Ssw[g + 8][k + t + 4]);
            uint32_t b[8][2];
            #pragma unroll
            for (int nb = 0; nb < 8; ++nb) {
                int n0 = nb * 8;
                b[nb][0] = __float_as_uint(Vs[n0 + g][k + t]);
                b[nb][1] = __float_as_uint(Vs[n0 + g][k + t + 4]);
            }
            #pragma unroll
            for (int nb = 0; nb < 8; ++nb)
                mma8(O[nb], a2, b[nb]);
        }
    }

    // ── row |S|-sum reduction within quad (lanes share rows across t) ──
    #pragma unroll
    for (int rh = 0; rh < 2; ++rh) {
        asum[rh] += __shfl_xor_sync(0xffffffffu, asum[rh], 1);
        asum[rh] += __shfl_xor_sync(0xffffffffu, asum[rh], 2);
    }

    #pragma unroll
    for (int rh = 0; rh < 2; ++rh) {
        float inv = 1.f / asum[rh];
        int l = q0 + wr + g + rh * 8;
        float* op = out + ((size_t)(n * SEQL + l)) * DMODEL + h * HDIM;
        #pragma unroll
        for (int nb = 0; nb < 8; ++nb) {
            int col = nb * 8 + 2 * t;
            float2 st;
            st.x = O[nb][rh * 2 + 0] * inv;
            st.y = O[nb][rh * 2 + 1] * inv;
            *(float2*)(op + col) = st;
        }
    }
}

// ─────────────────────────── launch ─────────────────────────────────────────
extern "C" void kernel_launch(void* const* d_in, const int* in_sizes, int n_in,
                              void* d_out, int out_size)
{
    const float* query = (const float*)d_in[0];
    const float* key   = (const float*)d_in[1];
    const float* Wq    = (const float*)d_in[2];
    const float* Wk    = (const float*)d_in[3];
    const float* Wv    = (const float*)d_in[4];
    const float* coeff = (const float*)d_in[5];
    const float* pw    = (const float*)d_in[6];
    const float* pb    = (const float*)d_in[7];
    float* out = (float*)d_out;

    cudaFuncSetAttribute(proj_tc, cudaFuncAttributeMaxDynamicSharedMemorySize, PJ_SMEM);
    cudaFuncSetAttribute(attn_tc, cudaFuncAttributeMaxDynamicSharedMemorySize, AT_SMEM);

    prepass_tc<<<dim3(256, 5), 256>>>(query, key, Wq, Wk, Wv);
    proj_tc<<<dim3(32, 4, 3), 256, PJ_SMEM>>>(coeff, pw, pb);
    attn_tc<<<dim3(32, 16), 128, AT_SMEM>>>(out);
}

// round 14
// speedup vs baseline: 1.1670x; 1.0267x over previous
#include <cuda_runtime.h>
#include <math.h>
#include <cstdint>

#define SEQL   2048
#define NHEAD  8
#define DMODEL 512
#define HDIM   64
#define CATD   128
#define NHTOT  16
#define XTOT   (4096 * DMODEL)     // one input tensor (N*L=4096 rows x 512)

// Scratch (allocation-free). All values stored pre-rounded to tf32 bit patterns.
__device__ float g_A [(size_t)NHTOT * SEQL * CATD];   // [nh][l][c]   attn A operand
__device__ float g_B [(size_t)NHTOT * SEQL * CATD];   // [nh][l][c]   attn B operand
__device__ float g_Vt[(size_t)NHTOT * HDIM * SEQL];   // [nh][d][l]   attn stage-2 B operand
__device__ float g_Xr[2 * XTOT];                      // tf32-rounded query | key
__device__ float g_Wr[3 * DMODEL * DMODEL];           // tf32-rounded Wq | Wk | Wv

#define DINL __device__ __forceinline__

DINL uint32_t f2tf(float f) {           // round fp32 -> tf32 (rna), fp32 bit layout
    uint32_t u;
    asm("cvt.rna.tf32.f32 %0, %1;" : "=r"(u) : "f"(f));
    return u;
}

// m16n8k8 tf32 MMA, fp32 accumulate (legacy mma.sync path, base sm_103 ISA)
DINL void mma8(float* d, const uint32_t* a, const uint32_t* b) {
    asm volatile("mma.sync.aligned.m16n8k8.row.col.f32.tf32.tf32.f32 "
        "{%0,%1,%2,%3}, {%4,%5,%6,%7}, {%8,%9}, {%0,%1,%2,%3};"
        : "+f"(d[0]), "+f"(d[1]), "+f"(d[2]), "+f"(d[3])
        : "r"(a[0]), "r"(a[1]), "r"(a[2]), "r"(a[3]), "r"(b[0]), "r"(b[1]));
}

// ldmatrix x4 (b16): 4 8x8 b16 matrices == 2 8x8 b32 tiles, or one 16x8 b32 tile.
DINL void ldsm4(uint32_t* r, uint32_t addr) {
    asm volatile("ldmatrix.sync.aligned.m8n8.x4.shared.b16 {%0,%1,%2,%3}, [%4];"
        : "=r"(r[0]), "=r"(r[1]), "=r"(r[2]), "=r"(r[3]) : "r"(addr));
}

DINL uint32_t smem_u32(const void* p) {
    uint32_t a;
    asm("{ .reg .u64 t; cvta.to.shared.u64 t, %1; cvt.u32.u64 %0, t; }" : "=r"(a) : "l"(p));
    return a;
}
DINL void cp16(uint32_t dst, const void* src) {
    asm volatile("cp.async.cg.shared.global [%0], [%1], 16;" :: "r"(dst), "l"(src));
}
#define CP_COMMIT() asm volatile("cp.async.commit_group;" ::: "memory")
#define CP_WAIT(N)  asm volatile("cp.async.wait_group %0;" :: "n"(N) : "memory")
#define CP_WAIT0()  asm volatile("cp.async.commit_group;\n\tcp.async.wait_group 0;" ::: "memory")

DINL float softplus_f(float x) {
    return fmaxf(x, 0.f) + log1pf(__expf(-fabsf(x)));
}
DINL void sincos_red(float ang, float* s, float* c) {
    const float INV2PI = 0.15915494309189535f;
    const float PI2_HI = 6.28318548202514648f;
    const float PI2_LO = -1.74845553e-7f;
    float k = rintf(ang * INV2PI);
    float r = fmaf(-k, PI2_HI, ang);
    r = fmaf(-k, PI2_LO, r);
    *s = __sinf(r);
    *c = __cosf(r);
}

// Lane-dependent ldmatrix address offsets (in elements, relative to tile origin):
//  b-style (two n-blocks of 8 rows x {colk,colk+4}): m0,m1 -> rows+0; m2,m3 -> rows+8
//  a-style (16 rows x {colk,colk+4}):                m0,m2 -> rows+0; m1,m3 -> rows+8
DINL int ldsm_b_row(int lane) { return (lane & 7) + ((lane >> 4) << 3); }
DINL int ldsm_b_col(int lane) { return ((lane >> 3) & 1) << 2; }
DINL int ldsm_a_row(int lane) { return (lane & 7) + (((lane >> 3) & 1) << 3); }
DINL int ldsm_a_col(int lane) { return (lane >> 4) << 2; }

// ─────────────────────────── Prepass: tf32-round inputs into scratch ────────
__global__ __launch_bounds__(256) void prepass_tc(
    const float* __restrict__ query, const float* __restrict__ key,
    const float* __restrict__ Wq, const float* __restrict__ Wk, const float* __restrict__ Wv)
{
    int sel = blockIdx.y;
    const float4* src;
    float4* dst;
    int cnt;
    if (sel == 0)      { src = (const float4*)query; dst = (float4*)g_Xr;          cnt = XTOT / 4; }
    else if (sel == 1) { src = (const float4*)key;   dst = (float4*)(g_Xr + XTOT); cnt = XTOT / 4; }
    else {
        int ws = sel - 2;
        src = (ws == 0) ? (const float4*)Wq : (ws == 1) ? (const float4*)Wk : (const float4*)Wv;
        dst = (float4*)(g_Wr + (size_t)ws * DMODEL * DMODEL);
        cnt = DMODEL * DMODEL / 4;
    }
    for (int i = blockIdx.x * blockDim.x + threadIdx.x; i < cnt; i += gridDim.x * blockDim.x) {
        float4 v = src[i];
        v.x = __uint_as_float(f2tf(v.x));
        v.y = __uint_as_float(f2tf(v.y));
        v.z = __uint_as_float(f2tf(v.z));
        v.w = __uint_as_float(f2tf(v.w));
        dst[i] = v;
    }
}

// ─────────────────────────── Projection GEMM (tf32 mma.sync, ldmatrix) ──────
// C(128x128) = X·W^T over K=512 in 16 slabs of K=32, double-buffered cp.async.
// 8 warps: 4(M) x 2(N), warp tile 32x64. All fragments via ldmatrix.x4.
#define PJ_PITCH 36
#define PJ_SLABF (128 * PJ_PITCH)
#define PJ_SMEM  (4 * PJ_SLABF * 4)          // 73728 bytes: X0|W0|X1|W1

DINL void pj_stage(uint32_t smu, const float* X, const float* W,
                   int m0, int c0, int s, int b, int tid)
{
    uint32_t xo = smu + (uint32_t)(2 * b * PJ_SLABF) * 4;
    uint32_t wo = xo + (uint32_t)PJ_SLABF * 4;
    #pragma unroll
    for (int it = 0; it < 4; ++it) {
        int idx = it * 256 + tid;
        int r = idx >> 3, c4 = (idx & 7) * 4;
        cp16(xo + (uint32_t)(r * PJ_PITCH + c4) * 4,
             X + (size_t)(m0 + r) * DMODEL + s * 32 + c4);
        cp16(wo + (uint32_t)(r * PJ_PITCH + c4) * 4,
             W + (size_t)(c0 + r) * DMODEL + s * 32 + c4);
    }
}

__global__ __launch_bounds__(256, 2) void proj_tc(
    const float* __restrict__ coeff, const float* __restrict__ pw, const float* __restrict__ pb)
{
    extern __shared__ float sm[];

    int tid = threadIdx.x, wid = tid >> 5, lane = tid & 31;
    int warpM = wid >> 1, warpN = wid & 1;
    int g = lane >> 2, t = lane & 3;
    int mode = blockIdx.z;
    const float* X = g_Xr + (mode == 0 ? 0 : XTOT);
    const float* W = g_Wr + (size_t)mode * DMODEL * DMODEL;
    int m0 = blockIdx.x * 128;
    int c0 = blockIdx.y * 128;
    uint32_t smu = smem_u32(sm);

    // ldmatrix per-lane bases (element offsets within a slab buffer)
    uint32_t xa_off = (uint32_t)((warpM * 32 + ldsm_a_row(lane)) * PJ_PITCH + ldsm_a_col(lane));
    uint32_t wb_off = (uint32_t)(PJ_SLABF + (warpN * 64 + ldsm_b_row(lane)) * PJ_PITCH + ldsm_b_col(lane));

    float acc[2][8][4];
    #pragma unroll
    for (int mb = 0; mb < 2; ++mb)
        #pragma unroll
        for (int nb = 0; nb < 8; ++nb)
            #pragma unroll
            for (int r = 0; r < 4; ++r) acc[mb][nb][r] = 0.f;

    pj_stage(smu, X, W, m0, c0, 0, 0, tid);
    CP_COMMIT();

    for (int s = 0; s < 16; ++s) {
        int cur = s & 1;
        if (s < 15) {
            pj_stage(smu, X, W, m0, c0, s + 1, cur ^ 1, tid);
            CP_COMMIT();
            CP_WAIT(1);
        } else {
            CP_WAIT(0);
        }
        __syncthreads();

        uint32_t buf = smu + (uint32_t)(2 * cur * PJ_SLABF) * 4;
        uint32_t xa = buf + xa_off * 4;
        uint32_t wb = buf + wb_off * 4;

        #pragma unroll
        for (int ks = 0; ks < 4; ++ks) {
            int k = ks * 8;
            uint32_t af[2][4];
            ldsm4(af[0], xa + (uint32_t)k * 4);
            ldsm4(af[1], xa + (uint32_t)(16 * PJ_PITCH + k) * 4);
            uint32_t bf[4][4];
            #pragma unroll
            for (int p = 0; p < 4; ++p)
                ldsm4(bf[p], wb + (uint32_t)(p * 16 * PJ_PITCH + k) * 4);
            #pragma unroll
            for (int mb = 0; mb < 2; ++mb)
                #pragma unroll
                for (int p = 0; p < 4; ++p) {
                    mma8(acc[mb][2 * p],     af[mb], &bf[p][0]);
                    mma8(acc[mb][2 * p + 1], af[mb], &bf[p][2]);
                }
        }
        __syncthreads();
    }

    // epilogue (unchanged numerics)
    #pragma unroll
    for (int mb = 0; mb < 2; ++mb) {
        #pragma unroll
        for (int nb = 0; nb < 8; ++nb) {
            #pragma unroll
            for (int r = 0; r < 4; ++r) {
                int row = warpM * 32 + mb * 16 + g + (r >> 1) * 8;
                int col = warpN * 64 + nb * 8 + 2 * t + (r & 1);
                int m = m0 + row;
                int n = m >> 11, l = m & (SEQL - 1);
                int c = c0 + col;
                int h = c >> 6, dd = c & 63;
                float x = acc[mb][nb][r];
                if (mode == 2) {
                    g_Vt[((size_t)((n * NHEAD + h) * HDIM + dd)) * SEQL + l] =
                        __uint_as_float(f2tf(x));
                } else {
                    size_t base = ((size_t)(n * NHEAD + h) * SEQL + l) * CATD;
                    float w = pw[c];
                    float sn, cs;
                    if (mode == 0) {
                        float sp = softplus_f(x);
                        sincos_red((float)l * w + pb[c], &sn, &cs);
                        g_A[base + dd]      = __uint_as_float(f2tf(sp * cs));
                        g_A[base + 64 + dd] = __uint_as_float(f2tf(sp * sn));
                    } else {
                        float sp = softplus_f(x) * coeff[c];
                        sincos_red((float)l * w, &sn, &cs);
                        g_B[base + dd]      = __uint_as_float(f2tf(sp * cs));
                        g_B[base + 64 + dd] = __uint_as_float(f2tf(sp * sn));
                    }
                }
            }
        }
    }
}

// ─────────────────────────── Attention (tf32 mma.sync, ldmatrix) ────────────
// R7 structure (128 thr, 4 warps, 16x64 warp tile, A-frags in regs, warp-private
// S, 3 CTAs/SM) with ALL fragment loads via ldmatrix.x4 (4x fewer smem instr).
#define AP 132
#define VP 68
#define SP 68
#define AT_BS_F   0
#define AT_VS_F   (64 * AP)                 // 8448
#define AT_SS_F   (64 * AP + 64 * VP)       // 12800
#define AT_SMEM   ((64 * AP + 64 * VP + 4 * 16 * SP) * 4)   // 68608 bytes

__global__ __launch_bounds__(128, 3) void attn_tc(float* __restrict__ out)
{
    extern __shared__ float sm[];
    float (*Vs)[VP] = (float(*)[VP])(sm + AT_VS_F);

    int tid = threadIdx.x, wid = tid >> 5, lane = tid & 31;
    int g = lane >> 2, t = lane & 3;
    int wr = wid * 16;                                  // warp's q-row base (local)
    float (*Ssw)[SP] = (float(*)[SP])(sm + AT_SS_F + wid * 16 * SP);  // warp-private

    int nh = blockIdx.y;
    int n = nh >> 3, h = nh & 7;
    int qt = (int)gridDim.x - 1 - (int)blockIdx.x;      // heavy tiles first
    int q0 = qt * 64;

    const float* Ab = g_A  + (size_t)nh * SEQL * CATD;
    const float* Bb = g_B  + (size_t)nh * SEQL * CATD;
    const float* Vb = g_Vt + (size_t)nh * HDIM * SEQL;

    uint32_t bs_u = smem_u32(sm);

    // ldmatrix per-lane bases
    uint32_t aA  = bs_u + (uint32_t)((wr + ldsm_a_row(lane)) * AP + ldsm_a_col(lane)) * 4;
    uint32_t bB  = bs_u + (uint32_t)(ldsm_b_row(lane) * AP + ldsm_b_col(lane)) * 4;
    uint32_t vB  = bs_u + (uint32_t)(AT_VS_F + ldsm_b_row(lane) * VP + ldsm_b_col(lane)) * 4;
    uint32_t sA  = bs_u + (uint32_t)(AT_SS_F + wid * 16 * SP
                                     + ldsm_a_row(lane) * SP + ldsm_a_col(lane)) * 4;

    // ── one-time: stage A tile (64x128) into Bs region, pull a-frags via ldsm ──
    #pragma unroll
    for (int it = 0; it < 16; ++it) {
        int idx = it * 128 + tid;
        int r = idx >> 5, c4 = (idx & 31) * 4;
        cp16(bs_u + (uint32_t)(r * AP + c4) * 4, Ab + (size_t)(q0 + r) * CATD + c4);
    }
    CP_WAIT0();
    __syncthreads();

    uint32_t a[16][4];
    #pragma unroll
    for (int ks = 0; ks < 16; ++ks)
        ldsm4(a[ks], aA + (uint32_t)(ks * 8) * 4);

    float O[8][4];
    #pragma unroll
    for (int nb = 0; nb < 8; ++nb)
        #pragma unroll
        for (int r = 0; r < 4; ++r) O[nb][r] = 0.f;
    float asum[2] = {0.f, 0.f};

    for (int kt = 0; kt <= qt; ++kt) {
        int k0 = kt * 64;
        __syncthreads();   // prior mma1/mma2 (and a-frag pulls, iter 0) done with Bs/Vs

        // ── stage B chunk (64x128) + V chunk (64x64) via cp.async ──
        #pragma unroll
        for (int it = 0; it < 16; ++it) {
            int idx = it * 128 + tid;
            int r = idx >> 5, c4 = (idx & 31) * 4;
            cp16(bs_u + (uint32_t)(r * AP + c4) * 4, Bb + (size_t)(k0 + r) * CATD + c4);
        }
        #pragma unroll
        for (int it = 0; it < 8; ++it) {
            int idx = it * 128 + tid;
            int r = idx >> 4, c4 = (idx & 15) * 4;
            cp16(bs_u + (uint32_t)(AT_VS_F + r * VP + c4) * 4,
                 Vb + (size_t)r * SEQL + k0 + c4);
        }
        CP_WAIT0();
        __syncthreads();

        // ── mma1: S(16x64) = A · B^T over catd=128 (b-frags via ldsm.x4) ──
        float S[8][4];
        #pragma unroll
        for (int nb = 0; nb < 8; ++nb)
            #pragma unroll
            for (int r = 0; r < 4; ++r) S[nb][r] = 0.f;

        #pragma unroll 4
        for (int ks = 0; ks < 16; ++ks) {
            int k = ks * 8;
            uint32_t bf[4][4];
            #pragma unroll
            for (int p = 0; p < 4; ++p)
                ldsm4(bf[p], bB + (uint32_t)(p * 16 * AP + k) * 4);
            #pragma unroll
            for (int p = 0; p < 4; ++p) {
                mma8(S[2 * p],     a[ks], &bf[p][0]);
                mma8(S[2 * p + 1], a[ks], &bf[p][2]);
            }
        }

        // ── epilogue: mask + |S| accumulation + S (tf32) into warp-private Ssw ──
        bool diag = (kt == qt);
        #pragma unroll
        for (int nb = 0; nb < 8; ++nb) {
            int col = nb * 8 + 2 * t;                   // local key col
            #pragma unroll
            for (int rh = 0; rh < 2; ++rh) {
                int rowl = g + rh * 8;                  // local row within warp tile
                float v0 = S[nb][rh * 2 + 0];
                float v1 = S[nb][rh * 2 + 1];
                if (diag) {
                    int qg = wr + rowl;                 // local q (k0 == q0 base)
                    if (col + 0 > qg) v0 = 0.f;
                    if (col + 1 > qg) v1 = 0.f;
                }
                asum[rh] += fabsf(v0) + fabsf(v1);
                float2 st;
                st.x = __uint_as_float(f2tf(v0));
                st.y = __uint_as_float(f2tf(v1));
                *(float2*)&Ssw[rowl][col] = st;
            }
        }
        __syncwarp();                                   // warp-private Ssw

        // ── mma2: O(16x64) += S · Vt^T over 64 keys (frags via ldsm.x4) ──
        #pragma unroll 4
        for (int ks = 0; ks < 8; ++ks) {
            int k = ks * 8;
            uint32_t a2[4];
            ldsm4(a2, sA + (uint32_t)k * 4);
            uint32_t bf[4][4];
            #pragma unroll
            for (int p = 0; p < 4; ++p)
                ldsm4(bf[p], vB + (uint32_t)(p * 16 * VP + k) * 4);
            #pragma unroll
            for (int p = 0; p < 4; ++p) {
                mma8(O[2 * p],     a2, &bf[p][0]);
                mma8(O[2 * p + 1], a2, &bf[p][2]);
            }
        }
    }

    // ── row |S|-sum reduction within quad (lanes share rows across t) ──
    #pragma unroll
    for (int rh = 0; rh < 2; ++rh) {
        asum[rh] += __shfl_xor_sync(0xffffffffu, asum[rh], 1);
        asum[rh] += __shfl_xor_sync(0xffffffffu, asum[rh], 2);
    }

    #pragma unroll
    for (int rh = 0; rh < 2; ++rh) {
        float inv = 1.f / asum[rh];
        int l = q0 + wr + g + rh * 8;
        float* op = out + ((size_t)(n * SEQL + l)) * DMODEL + h * HDIM;
        #pragma unroll
        for (int nb = 0; nb < 8; ++nb) {
            int col = nb * 8 + 2 * t;
            float2 st;
            st.x = O[nb][rh * 2 + 0] * inv;
            st.y = O[nb][rh * 2 + 1] * inv;
            *(float2*)(op + col) = st;
        }
    }
}

// ─────────────────────────── launch ─────────────────────────────────────────
extern "C" void kernel_launch(void* const* d_in, const int* in_sizes, int n_in,
                              void* d_out, int out_size)
{
    const float* query = (const float*)d_in[0];
    const float* key   = (const float*)d_in[1];
    const float* Wq    = (const float*)d_in[2];
    const float* Wk    = (const float*)d_in[3];
    const float* Wv    = (const float*)d_in[4];
    const float* coeff = (const float*)d_in[5];
    const float* pw    = (const float*)d_in[6];
    const float* pb    = (const float*)d_in[7];
    float* out = (float*)d_out;

    cudaFuncSetAttribute(proj_tc, cudaFuncAttributeMaxDynamicSharedMemorySize, PJ_SMEM);
    cudaFuncSetAttribute(attn_tc, cudaFuncAttributeMaxDynamicSharedMemorySize, AT_SMEM);

    prepass_tc<<<dim3(256, 5), 256>>>(query, key, Wq, Wk, Wv);
    proj_tc<<<dim3(32, 4, 3), 256, PJ_SMEM>>>(coeff, pw, pb);
    attn_tc<<<dim3(32, 16), 128, AT_SMEM>>>(out);
}